// round 12
// baseline (speedup 1.0000x reference)
#include <cuda_runtime.h>
#include <math.h>

#define NSEQ  4096
#define DIMM  1024
#define HEADS 16
#define HD    64
#define WIDTH 512
#define NW    8
#define NST   512
#define KEYW  1024

// ---------------- scratch ----------------
__device__ float g_xn[NSEQ*DIMM];
__device__ float g_qkv[NSEQ*3*DIMM];
__device__ float g_q2s[NSEQ*DIMM];
__device__ float g_state_qkv[NST*3*DIMM];
__device__ float g_st[NST*DIMM];
__device__ float g_qfs_raw[NST*DIMM];

__device__ float g_qn_main[HEADS*NSEQ*HD];
__device__ float g_kn_main[HEADS*NSEQ*HD];
__device__ float g_qn_ts[HEADS*NSEQ*HD];
__device__ float g_kn_ts[HEADS*NST*HD];
__device__ float g_qn_ss[HEADS*NST*HD];
__device__ float g_kn_ss[HEADS*NST*HD];
__device__ float g_qn_fs[HEADS*NST*HD];
__device__ float g_kn_fs[HEADS*NST*HD];

__device__ float g_cat[NSEQ*2*DIMM];       // [attn_out | ts_out]
__device__ float g_state_cat[NST*2*DIMM];
__device__ float g_so[NST*DIMM];
__device__ float g_z[NST*DIMM];

// ---------------- layernorm ----------------
__global__ void __launch_bounds__(256) ln_kernel(const float* __restrict__ x,
        const float* __restrict__ gamma, const float* __restrict__ pos,
        float* __restrict__ out)
{
    int row = blockIdx.x;
    const float* xr = x + (long)row*DIMM;
    float* orow = out + (long)row*DIMM;
    __shared__ float red[256];
    float s = 0.f, s2 = 0.f;
    for (int i = threadIdx.x; i < DIMM; i += 256) { float v = xr[i]; s += v; s2 += v*v; }
    red[threadIdx.x] = s; __syncthreads();
    for (int o = 128; o; o >>= 1) { if (threadIdx.x < o) red[threadIdx.x] += red[threadIdx.x+o]; __syncthreads(); }
    float mu = red[0] * (1.f/DIMM);
    __syncthreads();
    red[threadIdx.x] = s2; __syncthreads();
    for (int o = 128; o; o >>= 1) { if (threadIdx.x < o) red[threadIdx.x] += red[threadIdx.x+o]; __syncthreads(); }
    float var = red[0] * (1.f/DIMM) - mu*mu;
    float inv = rsqrtf(var + 1e-5f);
    for (int i = threadIdx.x; i < DIMM; i += 256) {
        float v = (xr[i]-mu)*inv*gamma[i];
        if (pos) v += pos[(long)row*DIMM + i];
        orow[i] = v;
    }
}

// ---------------- TF32 helpers ----------------
__device__ __forceinline__ unsigned f2tf32(float f)
{
    unsigned r;
    asm("cvt.rna.tf32.f32 %0, %1;" : "=r"(r) : "f"(f));
    return r;
}

__device__ __forceinline__ void mma_tf32(float c[4], const unsigned a[4], const unsigned b[2])
{
    asm volatile(
        "mma.sync.aligned.m16n8k8.row.col.f32.tf32.tf32.f32 "
        "{%0,%1,%2,%3}, {%4,%5,%6,%7}, {%8,%9}, {%0,%1,%2,%3};"
        : "+f"(c[0]), "+f"(c[1]), "+f"(c[2]), "+f"(c[3])
        : "r"(a[0]), "r"(a[1]), "r"(a[2]), "r"(a[3]), "r"(b[0]), "r"(b[1]));
}

__device__ __forceinline__ void cp16(float* dst, const float* src)
{
    unsigned d = (unsigned)__cvta_generic_to_shared(dst);
    asm volatile("cp.async.cg.shared.global [%0], [%1], 16;" :: "r"(d), "l"(src));
}

__device__ __forceinline__ void cp16p(float* dst, const float* src, int sz)
{
    unsigned d = (unsigned)__cvta_generic_to_shared(dst);
    asm volatile("cp.async.cg.shared.global [%0], [%1], 16, %2;" :: "r"(d), "l"(src), "r"(sz));
}

// ---------------- TF32 GEMM: cp.async 4-stage pipeline ----------------
#define TG_STAGES 4
#define TG_ASTRIDE 20
#define TG_ATILE (128*TG_ASTRIDE)
#define TG_BTILE (16*132)
#define TGEMM_SMEM (TG_STAGES*(TG_ATILE + TG_BTILE)*4)

__global__ void __launch_bounds__(256) tgemm(const float* __restrict__ A,
        const float* __restrict__ B, float* __restrict__ C,
        int M, int N, int K, int accum)
{
    extern __shared__ float tsm[];
    float* Asm = tsm;
    float* Bsm = tsm + TG_STAGES*TG_ATILE;

    int tid = threadIdx.x;
    int warp = tid >> 5, lane = tid & 31;
    int wy = warp >> 1, wx = warp & 1;
    int g = lane >> 2, t4 = lane & 3;
    int m0 = blockIdx.y*128, n0 = blockIdx.x*128;

    int nkt = K >> 4;

    auto issue = [&](int kt) {
        int buf = kt & (TG_STAGES-1);
        float* as = Asm + buf*TG_ATILE;
        float* bs = Bsm + buf*TG_BTILE;
        int row = tid >> 2, seg = (tid & 3)*4;
        const float* a0 = A + (long)(m0 + row)*K + kt*16 + seg;
        cp16(as + row*TG_ASTRIDE + seg, a0);
        cp16(as + (row+64)*TG_ASTRIDE + seg, a0 + (long)64*K);
        int krow = tid >> 5, col = (tid & 31)*4;
        const float* b0 = B + (long)(kt*16 + krow)*N + n0 + col;
        cp16(bs + krow*132 + col, b0);
        cp16(bs + (krow+8)*132 + col, b0 + (long)8*N);
        asm volatile("cp.async.commit_group;");
    };

    float acc[2][8][4];
    #pragma unroll
    for (int mi = 0; mi < 2; mi++)
        #pragma unroll
        for (int nj = 0; nj < 8; nj++)
            #pragma unroll
            for (int c = 0; c < 4; c++) acc[mi][nj][c] = 0.f;

    #pragma unroll
    for (int s = 0; s < TG_STAGES-1; s++)
        if (s < nkt) issue(s);

    for (int kt = 0; kt < nkt; kt++) {
        asm volatile("cp.async.wait_group %0;" :: "n"(TG_STAGES-2));
        __syncthreads();

        if (kt + TG_STAGES-1 < nkt) issue(kt + TG_STAGES-1);

        int buf = kt & (TG_STAGES-1);
        const float* as = Asm + buf*TG_ATILE;
        const float* bs = Bsm + buf*TG_BTILE;

        #pragma unroll
        for (int ks = 0; ks < 2; ks++) {
            int kk = ks*8;
            unsigned af[2][4], bf[8][2];
            #pragma unroll
            for (int mi = 0; mi < 2; mi++) {
                int mr = wy*32 + mi*16 + g;
                af[mi][0] = f2tf32(as[mr*TG_ASTRIDE + kk + t4]);
                af[mi][1] = f2tf32(as[(mr+8)*TG_ASTRIDE + kk + t4]);
                af[mi][2] = f2tf32(as[mr*TG_ASTRIDE + kk + t4 + 4]);
                af[mi][3] = f2tf32(as[(mr+8)*TG_ASTRIDE + kk + t4 + 4]);
            }
            #pragma unroll
            for (int nj = 0; nj < 8; nj++) {
                int nc = wx*64 + nj*8 + g;
                bf[nj][0] = f2tf32(bs[(kk + t4)*132 + nc]);
                bf[nj][1] = f2tf32(bs[(kk + t4 + 4)*132 + nc]);
            }
            #pragma unroll
            for (int mi = 0; mi < 2; mi++)
                #pragma unroll
                for (int nj = 0; nj < 8; nj++)
                    mma_tf32(acc[mi][nj], af[mi], bf[nj]);
        }
    }

    #pragma unroll
    for (int mi = 0; mi < 2; mi++) {
        #pragma unroll
        for (int nj = 0; nj < 8; nj++) {
            int row = m0 + wy*32 + mi*16 + g;
            int col = n0 + wx*64 + nj*8 + t4*2;
            float* p0 = &C[(long)row*N + col];
            float* p1 = &C[(long)(row+8)*N + col];
            float2 v0 = make_float2(acc[mi][nj][0], acc[mi][nj][1]);
            float2 v1 = make_float2(acc[mi][nj][2], acc[mi][nj][3]);
            if (accum) {
                float2 o0 = *(float2*)p0, o1 = *(float2*)p1;
                v0.x += o0.x; v0.y += o0.y; v1.x += o1.x; v1.y += o1.y;
            }
            *(float2*)p0 = v0;
            *(float2*)p1 = v1;
        }
    }
}

// ---------------- l2norm + scale, head-major ----------------
__global__ void norm_heads(const float* __restrict__ src, int srcStride, int colOff,
        int rowOff, const float* __restrict__ scale, float* __restrict__ dst, int nrows)
{
    int row = blockIdx.x, h = blockIdx.y, d = threadIdx.x;
    float v = src[(long)(rowOff+row)*srcStride + colOff + h*HD + d];
    float s = v*v;
    #pragma unroll
    for (int o = 16; o; o >>= 1) s += __shfl_xor_sync(0xffffffffu, s, o);
    __shared__ float sh[2];
    if ((d & 31) == 0) sh[d>>5] = s;
    __syncthreads();
    float inv = 1.f / fmaxf(sqrtf(sh[0]+sh[1]), 1e-12f);
    dst[((long)h*nrows + row)*HD + d] = v*inv*scale[d];
}

// ---------------- flash attention: 128-row tiles, raw Q/K/V, split at frag load ----------------
// QR [64 d][QPAD] raw; PT [64 key][QPAD] tf32 bits; KR [64 key][KPAD] raw; VR [64 key][KPAD] raw
#define QPAD 136
#define KPAD 68
#define FLASH_SMEM ((64*QPAD*2 + 64*KPAD*2)*4 + 512*4)

__global__ void __launch_bounds__(256, 2) flashmma(
        const float* __restrict__ Q, int qHeadRows,
        const float* __restrict__ Kh, int kHeadRows,
        const float* __restrict__ Vall, long vstride, int vColHeadMul, int vColAdd,
        int vRowExtra,
        const float* __restrict__ bias,
        float* __restrict__ Out, long ostride, int oColMul, int oColAdd,
        int L, int nwin)
{
    extern __shared__ float fsm[];
    float* QR = fsm;
    float* PT = fsm + 64*QPAD;
    float* KR = fsm + 2*64*QPAD;
    float* VR = fsm + 2*64*QPAD + 64*KPAD;
    float* SMAX = fsm + 2*64*QPAD + 2*64*KPAD;   // [128][2]
    float* SSUM = SMAX + 256;                     // [128][2]

    int tid = threadIdx.x;
    int warp = tid >> 5, lane = tid & 31;
    int wy = warp >> 1, wx = warp & 1;
    int g = lane >> 2, t4 = lane & 3;

    int z = blockIdx.y;
    int h = z / nwin, w = z - h*nwin;
    int winw = qHeadRows / nwin;
    int i0 = blockIdx.x*128;
    int qrow0 = w*winw + i0;
    int kOff = (nwin > 1) ? (w-1)*winw : 0;

    const float* Qblk = Q + ((long)h*qHeadRows + qrow0)*64;
    const float* Kbase = Kh + (long)h*kHeadRows*64;
    const float* Vbase = Vall + vColHeadMul*h + vColAdd;
    const float* biasH = bias ? bias + (long)h*WIDTH*KEYW : nullptr;

    auto issueK = [&](int c0) {
        #pragma unroll
        for (int t = 0; t < 4; t++) {
            int c4 = tid + t*256;
            int key = c4 >> 4, seg = (c4 & 15)*4;
            int kr = kOff + c0 + key;
            cp16p(KR + key*KPAD + seg, Kbase + (long)kr*64 + seg, (kr >= 0) ? 16 : 0);
        }
        asm volatile("cp.async.commit_group;");
    };
    auto issueV = [&](int c0) {
        #pragma unroll
        for (int t = 0; t < 4; t++) {
            int c4 = tid + t*256;
            int key = c4 >> 4, seg = (c4 & 15)*4;
            int kr = kOff + c0 + key;
            cp16p(VR + key*KPAD + seg, Vbase + (long)(kr + vRowExtra)*vstride + seg,
                  (kr >= 0) ? 16 : 0);
        }
        asm volatile("cp.async.commit_group;");
    };

    // prologue: start K(0), V(0) fetches, then stage Q (raw, [d][row])
    issueK(0);
    issueV(0);
    #pragma unroll
    for (int t = 0; t < 8; t++) {
        int e = tid + t*256;
        int r = e >> 4, c4 = (e & 15)*4;
        float4 v = *(const float4*)&Qblk[(long)r*64 + c4];
        QR[(c4+0)*QPAD + r] = v.x;
        QR[(c4+1)*QPAD + r] = v.y;
        QR[(c4+2)*QPAD + r] = v.z;
        QR[(c4+3)*QPAD + r] = v.w;
    }

    int mrb = wy*32 + g;     // base row within tile for this thread
    float m[4], l[4], acc[2][4][4];
    #pragma unroll
    for (int s = 0; s < 4; s++) { m[s] = -3.402823466e38f; l[s] = 0.f; }
    #pragma unroll
    for (int mi = 0; mi < 2; mi++)
        #pragma unroll
        for (int nj = 0; nj < 4; nj++)
            #pragma unroll
            for (int c = 0; c < 4; c++) acc[mi][nj][c] = 0.f;

    int Lq = biasH ? (i0 + 640) : L;
    if (Lq > L) Lq = L;
    int nch = (Lq + 63) >> 6;

    for (int ci = 0; ci < nch; ci++) {
        int c0 = ci << 6;
        bool more = (ci + 1 < nch);

        asm volatile("cp.async.wait_group 1;");   // K(ci) complete (V(ci) may pend)
        __syncthreads();                          // KR visible (+ QR on first iter)

        // ---- S = Q @ K^T (compensated; Q and K split at fragment load) ----
        float sf[2][4][4];
        #pragma unroll
        for (int mi = 0; mi < 2; mi++)
            #pragma unroll
            for (int nj = 0; nj < 4; nj++)
                #pragma unroll
                for (int c = 0; c < 4; c++) sf[mi][nj][c] = 0.f;

        #pragma unroll
        for (int kk = 0; kk < 64; kk += 8) {
            unsigned ahi[2][4], alo[2][4];
            #pragma unroll
            for (int mi = 0; mi < 2; mi++) {
                int mr = mrb + 16*mi;
                float r0 = QR[(kk+t4)*QPAD + mr];
                float r1 = QR[(kk+t4)*QPAD + mr + 8];
                float r2 = QR[(kk+t4+4)*QPAD + mr];
                float r3 = QR[(kk+t4+4)*QPAD + mr + 8];
                ahi[mi][0] = f2tf32(r0); alo[mi][0] = f2tf32(r0 - __uint_as_float(ahi[mi][0]));
                ahi[mi][1] = f2tf32(r1); alo[mi][1] = f2tf32(r1 - __uint_as_float(ahi[mi][1]));
                ahi[mi][2] = f2tf32(r2); alo[mi][2] = f2tf32(r2 - __uint_as_float(ahi[mi][2]));
                ahi[mi][3] = f2tf32(r3); alo[mi][3] = f2tf32(r3 - __uint_as_float(ahi[mi][3]));
            }
            #pragma unroll
            for (int nj = 0; nj < 4; nj++) {
                int nc = wx*32 + nj*8 + g;
                float k0 = KR[nc*KPAD + kk + t4];
                float k1 = KR[nc*KPAD + kk + t4 + 4];
                unsigned bhi[2] = { f2tf32(k0), f2tf32(k1) };
                unsigned blo[2] = { f2tf32(k0 - __uint_as_float(bhi[0])),
                                    f2tf32(k1 - __uint_as_float(bhi[1])) };
                #pragma unroll
                for (int mi = 0; mi < 2; mi++) {
                    mma_tf32(sf[mi][nj], ahi[mi], bhi);
                    mma_tf32(sf[mi][nj], alo[mi], bhi);
                    mma_tf32(sf[mi][nj], ahi[mi], blo);
                }
            }
        }

        // ---- scale + bias + mask ----
        #pragma unroll
        for (int mi = 0; mi < 2; mi++) {
            int ir0 = i0 + mrb + 16*mi, ir1 = ir0 + 8;
            #pragma unroll
            for (int nj = 0; nj < 4; nj++) {
                int j0 = c0 + wx*32 + nj*8 + 2*t4;
                #pragma unroll
                for (int c = 0; c < 4; c++) sf[mi][nj][c] *= 8.f;
                if (biasH) {
                    float2 b0 = *(const float2*)&biasH[(long)ir0*KEYW + j0];
                    float2 b1 = *(const float2*)&biasH[(long)ir1*KEYW + j0];
                    sf[mi][nj][0] += b0.x; sf[mi][nj][1] += b0.y;
                    sf[mi][nj][2] += b1.x; sf[mi][nj][3] += b1.y;
                    if (j0     > ir0 + 512) sf[mi][nj][0] = -3.402823466e38f;
                    if (j0 + 1 > ir0 + 512) sf[mi][nj][1] = -3.402823466e38f;
                    if (j0     > ir1 + 512) sf[mi][nj][2] = -3.402823466e38f;
                    if (j0 + 1 > ir1 + 512) sf[mi][nj][3] = -3.402823466e38f;
                }
            }
        }

        // ---- row max (4 rows per thread: s = 2*mi + sub) ----
        float pm[4];
        #pragma unroll
        for (int s = 0; s < 4; s++) pm[s] = -3.402823466e38f;
        #pragma unroll
        for (int mi = 0; mi < 2; mi++)
            #pragma unroll
            for (int nj = 0; nj < 4; nj++) {
                pm[2*mi]   = fmaxf(pm[2*mi],   fmaxf(sf[mi][nj][0], sf[mi][nj][1]));
                pm[2*mi+1] = fmaxf(pm[2*mi+1], fmaxf(sf[mi][nj][2], sf[mi][nj][3]));
            }
        #pragma unroll
        for (int s = 0; s < 4; s++) {
            pm[s] = fmaxf(pm[s], __shfl_xor_sync(0xffffffffu, pm[s], 1));
            pm[s] = fmaxf(pm[s], __shfl_xor_sync(0xffffffffu, pm[s], 2));
        }
        if (t4 == 0) {
            #pragma unroll
            for (int s = 0; s < 4; s++) {
                int ri = mrb + 16*(s>>1) + 8*(s&1);
                SMAX[ri*2 + wx] = pm[s];
            }
        }
        __syncthreads();                          // SMAX visible + all warps done with KR

        if (more) issueK(c0 + 64);                // KR free: prefetch next K

        float mn[4], corr[4];
        #pragma unroll
        for (int s = 0; s < 4; s++) {
            int ri = mrb + 16*(s>>1) + 8*(s&1);
            float cmax = fmaxf(SMAX[ri*2], SMAX[ri*2+1]);
            mn[s] = fmaxf(m[s], cmax);
            corr[s] = __expf(m[s] - mn[s]);
            m[s] = mn[s];
        }

        // exp + partial sums + write P transposed [key][row] (tf32 bits)
        float ps[4] = {0.f, 0.f, 0.f, 0.f};
        #pragma unroll
        for (int mi = 0; mi < 2; mi++) {
            int mr = mrb + 16*mi;
            #pragma unroll
            for (int nj = 0; nj < 4; nj++) {
                int j0 = wx*32 + nj*8 + 2*t4;
                float p00 = __expf(sf[mi][nj][0] - mn[2*mi]);
                float p01 = __expf(sf[mi][nj][1] - mn[2*mi]);
                float p10 = __expf(sf[mi][nj][2] - mn[2*mi+1]);
                float p11 = __expf(sf[mi][nj][3] - mn[2*mi+1]);
                ps[2*mi]   += p00 + p01;
                ps[2*mi+1] += p10 + p11;
                PT[j0*QPAD + mr]       = __uint_as_float(f2tf32(p00));
                PT[(j0+1)*QPAD + mr]   = __uint_as_float(f2tf32(p01));
                PT[j0*QPAD + mr+8]     = __uint_as_float(f2tf32(p10));
                PT[(j0+1)*QPAD + mr+8] = __uint_as_float(f2tf32(p11));
            }
        }
        #pragma unroll
        for (int s = 0; s < 4; s++) {
            ps[s] += __shfl_xor_sync(0xffffffffu, ps[s], 1);
            ps[s] += __shfl_xor_sync(0xffffffffu, ps[s], 2);
        }
        if (t4 == 0) {
            #pragma unroll
            for (int s = 0; s < 4; s++) {
                int ri = mrb + 16*(s>>1) + 8*(s&1);
                SSUM[ri*2 + wx] = ps[s];
            }
        }

        // rescale accumulators
        #pragma unroll
        for (int mi = 0; mi < 2; mi++)
            #pragma unroll
            for (int nj = 0; nj < 4; nj++) {
                acc[mi][nj][0] *= corr[2*mi];   acc[mi][nj][1] *= corr[2*mi];
                acc[mi][nj][2] *= corr[2*mi+1]; acc[mi][nj][3] *= corr[2*mi+1];
            }

        if (more) { asm volatile("cp.async.wait_group 1;"); }   // V(ci) done (K(ci+1) may pend)
        else      { asm volatile("cp.async.wait_group 0;"); }
        __syncthreads();                          // PT + SSUM + VR visible

        #pragma unroll
        for (int s = 0; s < 4; s++) {
            int ri = mrb + 16*(s>>1) + 8*(s&1);
            l[s] = l[s]*corr[s] + SSUM[ri*2] + SSUM[ri*2+1];
        }

        // ---- acc += P @ V (single tf32) ----
        #pragma unroll
        for (int kk = 0; kk < 64; kk += 8) {
            unsigned ap[2][4];
            #pragma unroll
            for (int mi = 0; mi < 2; mi++) {
                int mr = mrb + 16*mi;
                ap[mi][0] = __float_as_uint(PT[(kk+t4)*QPAD + mr]);
                ap[mi][1] = __float_as_uint(PT[(kk+t4)*QPAD + mr + 8]);
                ap[mi][2] = __float_as_uint(PT[(kk+t4+4)*QPAD + mr]);
                ap[mi][3] = __float_as_uint(PT[(kk+t4+4)*QPAD + mr + 8]);
            }
            #pragma unroll
            for (int nj = 0; nj < 4; nj++) {
                int nc = wx*32 + nj*8 + g;
                unsigned bv[2] = { f2tf32(VR[(kk+t4)*KPAD + nc]),
                                   f2tf32(VR[(kk+t4+4)*KPAD + nc]) };
                #pragma unroll
                for (int mi = 0; mi < 2; mi++)
                    mma_tf32(acc[mi][nj], ap[mi], bv);
            }
        }
        __syncthreads();                          // PT/VR free before next chunk's writes
        if (more) issueV(c0 + 64);
    }

    // epilogue
    float inv[4];
    #pragma unroll
    for (int s = 0; s < 4; s++) inv[s] = 1.f / l[s];
    #pragma unroll
    for (int mi = 0; mi < 2; mi++) {
        #pragma unroll
        for (int nj = 0; nj < 4; nj++) {
            int col = h*oColMul + oColAdd + wx*32 + nj*8 + 2*t4;
            long r0 = (long)(qrow0 + mrb + 16*mi)*ostride + col;
            long r1 = (long)(qrow0 + mrb + 16*mi + 8)*ostride + col;
            *(float2*)&Out[r0] = make_float2(acc[mi][nj][0]*inv[2*mi],
                                             acc[mi][nj][1]*inv[2*mi]);
            *(float2*)&Out[r1] = make_float2(acc[mi][nj][2]*inv[2*mi+1],
                                             acc[mi][nj][3]*inv[2*mi+1]);
        }
    }
}

// ---------------- memories copy ----------------
__global__ void memories_kernel(const float* __restrict__ qkv, float* __restrict__ out)
{
    int idx = blockIdx.x*256 + threadIdx.x;
    if (idx >= 2*HEADS*WIDTH*HD) return;
    int d = idx & 63;
    int i = (idx >> 6) & 511;
    int h = (idx >> 15) & 15;
    int s = idx >> 19;
    out[idx] = qkv[(long)(3584+i)*3072 + (s ? 2048 : 1024) + h*HD + d];
}

// ---------------- new_states ----------------
__global__ void newstates_kernel(const float* __restrict__ gz, const float* __restrict__ bg,
        const float* __restrict__ beta, const float* __restrict__ init_state,
        float* __restrict__ out)
{
    int idx = blockIdx.x*256 + threadIdx.x;
    if (idx >= NST*DIMM) return;
    int c = idx & (DIMM-1);
    float sig = 1.f/(1.f+expf(-beta[c]));
    float z = gz[idx] + bg[c];
    out[idx] = sig*z + (1.f-sig)*init_state[idx];
}

// ---------------- host launch ----------------
static float* symaddr(const void* s)
{
    void* p = nullptr;
    cudaGetSymbolAddress(&p, s);
    return (float*)p;
}

extern "C" void kernel_launch(void* const* d_in, const int* in_sizes, int n_in,
                              void* d_out, int out_size)
{
    const float* x       = (const float*)d_in[0];
    const float* bias    = (const float*)d_in[1];
    const float* gamma   = (const float*)d_in[2];
    const float* w_qkv   = (const float*)d_in[3];
    const float* q_scale = (const float*)d_in[4];
    const float* k_scale = (const float*)d_in[5];
    const float* w_out   = (const float*)d_in[6];
    const float* s_gamma = (const float*)d_in[7];
    const float* w_q2s   = (const float*)d_in[8];
    const float* w_qfs   = (const float*)d_in[9];
    const float* w_sqkv  = (const float*)d_in[10];
    const float* init_st = (const float*)d_in[11];
    const float* pos_ids = (const float*)d_in[12];
    const float* w_sout  = (const float*)d_in[13];
    const float* ts_q    = (const float*)d_in[14];
    const float* ts_k    = (const float*)d_in[15];
    const float* ss_q    = (const float*)d_in[16];
    const float* ss_k    = (const float*)d_in[17];
    const float* fs_q    = (const float*)d_in[18];
    const float* fs_k    = (const float*)d_in[19];
    const float* w_gate  = (const float*)d_in[20];
    const float* b_gate  = (const float*)d_in[21];
    const float* beta    = (const float*)d_in[22];
    float* out = (float*)d_out;

    float* xn   = symaddr(g_xn);
    float* qkv  = symaddr(g_qkv);
    float* q2s  = symaddr(g_q2s);
    float* sqkv = symaddr(g_state_qkv);
    float* st   = symaddr(g_st);
    float* qfsr = symaddr(g_qfs_raw);
    float* qnm  = symaddr(g_qn_main);
    float* knm  = symaddr(g_kn_main);
    float* qnts = symaddr(g_qn_ts);
    float* knts = symaddr(g_kn_ts);
    float* qnss = symaddr(g_qn_ss);
    float* knss = symaddr(g_kn_ss);
    float* qnfs = symaddr(g_qn_fs);
    float* knfs = symaddr(g_kn_fs);
    float* cat  = symaddr(g_cat);
    float* scat = symaddr(g_state_cat);
    float* so   = symaddr(g_so);
    float* zb   = symaddr(g_z);

    cudaFuncSetAttribute(flashmma, cudaFuncAttributeMaxDynamicSharedMemorySize, FLASH_SMEM);
    cudaFuncSetAttribute(tgemm, cudaFuncAttributeMaxDynamicSharedMemorySize, TGEMM_SMEM);

    // 1) layernorms
    ln_kernel<<<NSEQ, 256>>>(x, gamma, nullptr, xn);
    ln_kernel<<<NST, 256>>>(init_st, s_gamma, pos_ids, st);

    // 2) projections
    tgemm<<<dim3(3072/128, NSEQ/128), 256, TGEMM_SMEM>>>(xn, w_qkv, qkv, NSEQ, 3072, DIMM, 0);
    tgemm<<<dim3(DIMM/128, NSEQ/128), 256, TGEMM_SMEM>>>(xn, w_q2s, q2s, NSEQ, DIMM, DIMM, 0);
    tgemm<<<dim3(3072/128, NST/128), 256, TGEMM_SMEM>>>(init_st, w_sqkv, sqkv, NST, 3072, DIMM, 0);
    tgemm<<<dim3(DIMM/128, NST/128), 256, TGEMM_SMEM>>>(st, w_qfs, qfsr, NST, DIMM, DIMM, 0);

    // 3) l2norm + scale, head-major
    norm_heads<<<dim3(NSEQ, HEADS), 64>>>(qkv, 3072, 0,    0,    q_scale, qnm,  NSEQ);
    norm_heads<<<dim3(NSEQ, HEADS), 64>>>(qkv, 3072, 1024, 0,    k_scale, knm,  NSEQ);
    norm_heads<<<dim3(NSEQ, HEADS), 64>>>(q2s, 1024, 0,    0,    ts_q,    qnts, NSEQ);
    norm_heads<<<dim3(NST,  HEADS), 64>>>(sqkv, 3072, 1024, 0,   ts_k,    knts, NST);
    norm_heads<<<dim3(NST,  HEADS), 64>>>(sqkv, 3072, 0,    0,   ss_q,    qnss, NST);
    norm_heads<<<dim3(NST,  HEADS), 64>>>(sqkv, 3072, 1024, 0,   ss_k,    knss, NST);
    norm_heads<<<dim3(NST,  HEADS), 64>>>(qfsr, 1024, 0,    0,   fs_q,    qnfs, NST);
    norm_heads<<<dim3(NST,  HEADS), 64>>>(qkv,  3072, 1024, 3584, fs_k,   knfs, NST);

    // 4) fused attentions (128-row q tiles)
    flashmma<<<dim3(WIDTH/128, HEADS*NW), 256, FLASH_SMEM>>>(
        qnm, NSEQ, knm, NSEQ, qkv, 3072, HD, 2048, 0, bias,
        cat, 2*DIMM, HD, 0, KEYW, NW);
    flashmma<<<dim3(NSEQ/128, HEADS), 256, FLASH_SMEM>>>(
        qnts, NSEQ, knts, NST, sqkv, 3072, HD, 2048, 0, nullptr,
        cat, 2*DIMM, HD, DIMM, NST, 1);
    flashmma<<<dim3(NST/128, HEADS), 256, FLASH_SMEM>>>(
        qnss, NST, knss, NST, sqkv, 3072, HD, 2048, 0, nullptr,
        scat, 2*DIMM, 2*HD, 0, NST, 1);
    flashmma<<<dim3(NST/128, HEADS), 256, FLASH_SMEM>>>(
        qnfs, NST, knfs, NST, qkv, 3072, HD, 2048, 3584, nullptr,
        scat, 2*DIMM, 2*HD, HD, NST, 1);

    // 5) output projection: out = cat @ w_out (single K=2048 GEMM)
    tgemm<<<dim3(DIMM/128, NSEQ/128), 256, TGEMM_SMEM>>>(cat, w_out, out, NSEQ, DIMM, 2*DIMM, 0);

    // 6) memories
    memories_kernel<<<(2*HEADS*WIDTH*HD)/256, 256>>>(qkv, out + (long)NSEQ*DIMM);

    // 7) state output path
    tgemm<<<dim3(DIMM/128, NST/128), 256, TGEMM_SMEM>>>(scat, w_sout, so, NST, DIMM, 2*DIMM, 0);
    tgemm<<<dim3(DIMM/128, NST/128), 256, TGEMM_SMEM>>>(so, w_gate, zb, NST, DIMM, DIMM, 0);
    newstates_kernel<<<(NST*DIMM)/256, 256>>>(zb, b_gate, beta, init_st,
            out + (long)NSEQ*DIMM + 2*HEADS*WIDTH*HD);
}

// round 13
// speedup vs baseline: 1.1715x; 1.1715x over previous
#include <cuda_runtime.h>
#include <math.h>

#define NSEQ  4096
#define DIMM  1024
#define HEADS 16
#define HD    64
#define WIDTH 512
#define NW    8
#define NST   512
#define KEYW  1024

// ---------------- scratch ----------------
__device__ float g_xn[NSEQ*DIMM];
__device__ float g_qkv[NSEQ*3*DIMM];
__device__ float g_q2s[NSEQ*DIMM];
__device__ float g_state_qkv[NST*3*DIMM];
__device__ float g_st[NST*DIMM];
__device__ float g_qfs_raw[NST*DIMM];

__device__ float g_qn_main[HEADS*NSEQ*HD];
__device__ float g_kn_main[HEADS*NSEQ*HD];
__device__ float g_qn_ts[HEADS*NSEQ*HD];
__device__ float g_kn_ts[HEADS*NST*HD];
__device__ float g_qn_ss[HEADS*NST*HD];
__device__ float g_kn_ss[HEADS*NST*HD];
__device__ float g_qn_fs[HEADS*NST*HD];
__device__ float g_kn_fs[HEADS*NST*HD];

__device__ float g_cat[NSEQ*2*DIMM];
__device__ float g_state_cat[NST*2*DIMM];
__device__ float g_so[NST*DIMM];
__device__ float g_z[NST*DIMM];

// ---------------- layernorm ----------------
__global__ void __launch_bounds__(256) ln_kernel(const float* __restrict__ x,
        const float* __restrict__ gamma, const float* __restrict__ pos,
        float* __restrict__ out)
{
    int row = blockIdx.x;
    const float* xr = x + (long)row*DIMM;
    float* orow = out + (long)row*DIMM;
    __shared__ float red[256];
    float s = 0.f, s2 = 0.f;
    for (int i = threadIdx.x; i < DIMM; i += 256) { float v = xr[i]; s += v; s2 += v*v; }
    red[threadIdx.x] = s; __syncthreads();
    for (int o = 128; o; o >>= 1) { if (threadIdx.x < o) red[threadIdx.x] += red[threadIdx.x+o]; __syncthreads(); }
    float mu = red[0] * (1.f/DIMM);
    __syncthreads();
    red[threadIdx.x] = s2; __syncthreads();
    for (int o = 128; o; o >>= 1) { if (threadIdx.x < o) red[threadIdx.x] += red[threadIdx.x+o]; __syncthreads(); }
    float var = red[0] * (1.f/DIMM) - mu*mu;
    float inv = rsqrtf(var + 1e-5f);
    for (int i = threadIdx.x; i < DIMM; i += 256) {
        float v = (xr[i]-mu)*inv*gamma[i];
        if (pos) v += pos[(long)row*DIMM + i];
        orow[i] = v;
    }
}

// ---------------- TF32 helpers ----------------
__device__ __forceinline__ unsigned f2tf32(float f)
{
    unsigned r;
    asm("cvt.rna.tf32.f32 %0, %1;" : "=r"(r) : "f"(f));
    return r;
}

__device__ __forceinline__ void mma_tf32(float c[4], const unsigned a[4], const unsigned b[2])
{
    asm volatile(
        "mma.sync.aligned.m16n8k8.row.col.f32.tf32.tf32.f32 "
        "{%0,%1,%2,%3}, {%4,%5,%6,%7}, {%8,%9}, {%0,%1,%2,%3};"
        : "+f"(c[0]), "+f"(c[1]), "+f"(c[2]), "+f"(c[3])
        : "r"(a[0]), "r"(a[1]), "r"(a[2]), "r"(a[3]), "r"(b[0]), "r"(b[1]));
}

__device__ __forceinline__ void cp16(float* dst, const float* src)
{
    unsigned d = (unsigned)__cvta_generic_to_shared(dst);
    asm volatile("cp.async.cg.shared.global [%0], [%1], 16;" :: "r"(d), "l"(src));
}

__device__ __forceinline__ void cp16p(float* dst, const float* src, int sz)
{
    unsigned d = (unsigned)__cvta_generic_to_shared(dst);
    asm volatile("cp.async.cg.shared.global [%0], [%1], 16, %2;" :: "r"(d), "l"(src), "r"(sz));
}

// ---------------- TF32 GEMM: cp.async 4-stage pipeline ----------------
#define TG_STAGES 4
#define TG_ASTRIDE 20
#define TG_ATILE (128*TG_ASTRIDE)
#define TG_BTILE (16*132)
#define TGEMM_SMEM (TG_STAGES*(TG_ATILE + TG_BTILE)*4)

__global__ void __launch_bounds__(256) tgemm(const float* __restrict__ A,
        const float* __restrict__ B, float* __restrict__ C,
        int M, int N, int K, int accum)
{
    extern __shared__ float tsm[];
    float* Asm = tsm;
    float* Bsm = tsm + TG_STAGES*TG_ATILE;

    int tid = threadIdx.x;
    int warp = tid >> 5, lane = tid & 31;
    int wy = warp >> 1, wx = warp & 1;
    int g = lane >> 2, t4 = lane & 3;
    int m0 = blockIdx.y*128, n0 = blockIdx.x*128;

    int nkt = K >> 4;

    auto issue = [&](int kt) {
        int buf = kt & (TG_STAGES-1);
        float* as = Asm + buf*TG_ATILE;
        float* bs = Bsm + buf*TG_BTILE;
        int row = tid >> 2, seg = (tid & 3)*4;
        const float* a0 = A + (long)(m0 + row)*K + kt*16 + seg;
        cp16(as + row*TG_ASTRIDE + seg, a0);
        cp16(as + (row+64)*TG_ASTRIDE + seg, a0 + (long)64*K);
        int krow = tid >> 5, col = (tid & 31)*4;
        const float* b0 = B + (long)(kt*16 + krow)*N + n0 + col;
        cp16(bs + krow*132 + col, b0);
        cp16(bs + (krow+8)*132 + col, b0 + (long)8*N);
        asm volatile("cp.async.commit_group;");
    };

    float acc[2][8][4];
    #pragma unroll
    for (int mi = 0; mi < 2; mi++)
        #pragma unroll
        for (int nj = 0; nj < 8; nj++)
            #pragma unroll
            for (int c = 0; c < 4; c++) acc[mi][nj][c] = 0.f;

    #pragma unroll
    for (int s = 0; s < TG_STAGES-1; s++)
        if (s < nkt) issue(s);

    for (int kt = 0; kt < nkt; kt++) {
        asm volatile("cp.async.wait_group %0;" :: "n"(TG_STAGES-2));
        __syncthreads();

        if (kt + TG_STAGES-1 < nkt) issue(kt + TG_STAGES-1);

        int buf = kt & (TG_STAGES-1);
        const float* as = Asm + buf*TG_ATILE;
        const float* bs = Bsm + buf*TG_BTILE;

        #pragma unroll
        for (int ks = 0; ks < 2; ks++) {
            int kk = ks*8;
            unsigned af[2][4], bf[8][2];
            #pragma unroll
            for (int mi = 0; mi < 2; mi++) {
                int mr = wy*32 + mi*16 + g;
                af[mi][0] = f2tf32(as[mr*TG_ASTRIDE + kk + t4]);
                af[mi][1] = f2tf32(as[(mr+8)*TG_ASTRIDE + kk + t4]);
                af[mi][2] = f2tf32(as[mr*TG_ASTRIDE + kk + t4 + 4]);
                af[mi][3] = f2tf32(as[(mr+8)*TG_ASTRIDE + kk + t4 + 4]);
            }
            #pragma unroll
            for (int nj = 0; nj < 8; nj++) {
                int nc = wx*64 + nj*8 + g;
                bf[nj][0] = f2tf32(bs[(kk + t4)*132 + nc]);
                bf[nj][1] = f2tf32(bs[(kk + t4 + 4)*132 + nc]);
            }
            #pragma unroll
            for (int mi = 0; mi < 2; mi++)
                #pragma unroll
                for (int nj = 0; nj < 8; nj++)
                    mma_tf32(acc[mi][nj], af[mi], bf[nj]);
        }
    }

    #pragma unroll
    for (int mi = 0; mi < 2; mi++) {
        #pragma unroll
        for (int nj = 0; nj < 8; nj++) {
            int row = m0 + wy*32 + mi*16 + g;
            int col = n0 + wx*64 + nj*8 + t4*2;
            float* p0 = &C[(long)row*N + col];
            float* p1 = &C[(long)(row+8)*N + col];
            float2 v0 = make_float2(acc[mi][nj][0], acc[mi][nj][1]);
            float2 v1 = make_float2(acc[mi][nj][2], acc[mi][nj][3]);
            if (accum) {
                float2 o0 = *(float2*)p0, o1 = *(float2*)p1;
                v0.x += o0.x; v0.y += o0.y; v1.x += o1.x; v1.y += o1.y;
            }
            *(float2*)p0 = v0;
            *(float2*)p1 = v1;
        }
    }
}

// ---------------- l2norm + scale, head-major ----------------
__global__ void norm_heads(const float* __restrict__ src, int srcStride, int colOff,
        int rowOff, const float* __restrict__ scale, float* __restrict__ dst, int nrows)
{
    int row = blockIdx.x, h = blockIdx.y, d = threadIdx.x;
    float v = src[(long)(rowOff+row)*srcStride + colOff + h*HD + d];
    float s = v*v;
    #pragma unroll
    for (int o = 16; o; o >>= 1) s += __shfl_xor_sync(0xffffffffu, s, o);
    __shared__ float sh[2];
    if ((d & 31) == 0) sh[d>>5] = s;
    __syncthreads();
    float inv = 1.f / fmaxf(sqrtf(sh[0]+sh[1]), 1e-12f);
    dst[((long)h*nrows + row)*HD + d] = v*inv*scale[d];
}

// ---------------- flash attention: cp.async K/V raw, split at fragment load (R10) ----------------
#define FPAD 68
#define TILEU (64*FPAD)
#define FLASH_SMEM (6*TILEU*4 + 256*4)

__global__ void __launch_bounds__(256, 2) flashmma(
        const float* __restrict__ Q, int qHeadRows,
        const float* __restrict__ Kh, int kHeadRows,
        const float* __restrict__ Vall, long vstride, int vColHeadMul, int vColAdd,
        int vRowExtra,
        const float* __restrict__ bias,
        float* __restrict__ Out, long ostride, int oColMul, int oColAdd,
        int L, int nwin)
{
    extern __shared__ unsigned usm[];
    unsigned* QHI = usm;
    unsigned* QLO = usm + TILEU;
    float* KR  = (float*)(usm + 2*TILEU);
    float* VR0 = (float*)(usm + 3*TILEU);
    float* VR1 = (float*)(usm + 4*TILEU);
    unsigned* PT = usm + 5*TILEU;
    float* SMAX = (float*)(usm + 6*TILEU);
    float* SSUM = SMAX + 128;

    int tid = threadIdx.x;
    int warp = tid >> 5, lane = tid & 31;
    int wy = warp >> 1, wx = warp & 1;
    int g = lane >> 2, t4 = lane & 3;

    int z = blockIdx.y;
    int h = z / nwin, w = z - h*nwin;
    int winw = qHeadRows / nwin;
    int i0 = blockIdx.x*64;
    int qrow0 = w*winw + i0;
    int kOff = (nwin > 1) ? (w-1)*winw : 0;

    const float* Qblk = Q + ((long)h*qHeadRows + qrow0)*64;
    const float* Kbase = Kh + (long)h*kHeadRows*64;
    const float* Vbase = Vall + vColHeadMul*h + vColAdd;
    const float* biasH = bias ? bias + (long)h*WIDTH*KEYW : nullptr;

    auto issueK = [&](int c0) {
        #pragma unroll
        for (int t = 0; t < 4; t++) {
            int c4 = tid + t*256;
            int key = c4 >> 4, seg = (c4 & 15)*4;
            int kr = kOff + c0 + key;
            cp16p(KR + key*FPAD + seg, Kbase + (long)kr*64 + seg, (kr >= 0) ? 16 : 0);
        }
        asm volatile("cp.async.commit_group;");
    };
    auto issueV = [&](int c0, float* VB) {
        #pragma unroll
        for (int t = 0; t < 4; t++) {
            int c4 = tid + t*256;
            int key = c4 >> 4, seg = (c4 & 15)*4;
            int kr = kOff + c0 + key;
            cp16p(VB + key*FPAD + seg, Vbase + (long)(kr + vRowExtra)*vstride + seg,
                  (kr >= 0) ? 16 : 0);
        }
        asm volatile("cp.async.commit_group;");
    };

    #pragma unroll
    for (int t = 0; t < 16; t++) {
        int e = tid + t*256;
        int r = e >> 6, c = e & 63;
        float v = Qblk[(long)r*64 + c];
        unsigned hi = f2tf32(v);
        QHI[c*FPAD + r] = hi;
        QLO[c*FPAD + r] = f2tf32(v - __uint_as_float(hi));
    }

    int mr = wy*16 + g;
    float m0r = -3.402823466e38f, m1r = -3.402823466e38f;
    float l0 = 0.f, l1 = 0.f;
    float acc[4][4];
    #pragma unroll
    for (int nj = 0; nj < 4; nj++)
        #pragma unroll
        for (int c = 0; c < 4; c++) acc[nj][c] = 0.f;

    int Lq = biasH ? (i0 + 576) : L;
    if (Lq > L) Lq = L;
    int nch = (Lq + 63) >> 6;

    issueV(0, VR0);
    issueK(0);

    for (int ci = 0; ci < nch; ci++) {
        int c0 = ci << 6;
        float* VB = (ci & 1) ? VR1 : VR0;
        bool more = (ci + 1 < nch);

        if (more) {
            issueV(c0 + 64, (ci & 1) ? VR0 : VR1);
            asm volatile("cp.async.wait_group 1;");
        } else {
            asm volatile("cp.async.wait_group 0;");
        }
        __syncthreads();

        float sf[4][4];
        #pragma unroll
        for (int nj = 0; nj < 4; nj++)
            #pragma unroll
            for (int c = 0; c < 4; c++) sf[nj][c] = 0.f;

        #pragma unroll
        for (int kk = 0; kk < 64; kk += 8) {
            unsigned ahi[4], alo[4];
            ahi[0] = QHI[(kk+t4)*FPAD + mr];
            ahi[1] = QHI[(kk+t4)*FPAD + mr + 8];
            ahi[2] = QHI[(kk+t4+4)*FPAD + mr];
            ahi[3] = QHI[(kk+t4+4)*FPAD + mr + 8];
            alo[0] = QLO[(kk+t4)*FPAD + mr];
            alo[1] = QLO[(kk+t4)*FPAD + mr + 8];
            alo[2] = QLO[(kk+t4+4)*FPAD + mr];
            alo[3] = QLO[(kk+t4+4)*FPAD + mr + 8];
            #pragma unroll
            for (int nj = 0; nj < 4; nj++) {
                int nc = wx*32 + nj*8 + g;
                float k0 = KR[nc*FPAD + kk + t4];
                float k1 = KR[nc*FPAD + kk + t4 + 4];
                unsigned bhi[2] = { f2tf32(k0), f2tf32(k1) };
                unsigned blo[2] = { f2tf32(k0 - __uint_as_float(bhi[0])),
                                    f2tf32(k1 - __uint_as_float(bhi[1])) };
                mma_tf32(sf[nj], ahi, bhi);
                mma_tf32(sf[nj], alo, bhi);
                mma_tf32(sf[nj], ahi, blo);
            }
        }

        int ir0 = i0 + mr, ir1 = ir0 + 8;
        #pragma unroll
        for (int nj = 0; nj < 4; nj++) {
            int j0 = c0 + wx*32 + nj*8 + 2*t4;
            #pragma unroll
            for (int c = 0; c < 4; c++) sf[nj][c] *= 8.f;
            if (biasH) {
                float2 b0 = *(const float2*)&biasH[(long)ir0*KEYW + j0];
                float2 b1 = *(const float2*)&biasH[(long)ir1*KEYW + j0];
                sf[nj][0] += b0.x; sf[nj][1] += b0.y;
                sf[nj][2] += b1.x; sf[nj][3] += b1.y;
                if (j0     > ir0 + 512) sf[nj][0] = -3.402823466e38f;
                if (j0 + 1 > ir0 + 512) sf[nj][1] = -3.402823466e38f;
                if (j0     > ir1 + 512) sf[nj][2] = -3.402823466e38f;
                if (j0 + 1 > ir1 + 512) sf[nj][3] = -3.402823466e38f;
            }
        }

        float pm0 = -3.402823466e38f, pm1 = -3.402823466e38f;
        #pragma unroll
        for (int nj = 0; nj < 4; nj++) {
            pm0 = fmaxf(pm0, fmaxf(sf[nj][0], sf[nj][1]));
            pm1 = fmaxf(pm1, fmaxf(sf[nj][2], sf[nj][3]));
        }
        pm0 = fmaxf(pm0, __shfl_xor_sync(0xffffffffu, pm0, 1));
        pm0 = fmaxf(pm0, __shfl_xor_sync(0xffffffffu, pm0, 2));
        pm1 = fmaxf(pm1, __shfl_xor_sync(0xffffffffu, pm1, 1));
        pm1 = fmaxf(pm1, __shfl_xor_sync(0xffffffffu, pm1, 2));
        if (t4 == 0) {
            SMAX[mr*2 + wx] = pm0;
            SMAX[(mr+8)*2 + wx] = pm1;
        }
        __syncthreads();

        if (more) issueK(c0 + 64);

        float cmax0 = fmaxf(SMAX[mr*2], SMAX[mr*2+1]);
        float cmax1 = fmaxf(SMAX[(mr+8)*2], SMAX[(mr+8)*2+1]);

        float mn0 = fmaxf(m0r, cmax0);
        float mn1 = fmaxf(m1r, cmax1);
        float corr0 = __expf(m0r - mn0);
        float corr1 = __expf(m1r - mn1);
        m0r = mn0; m1r = mn1;

        float ps0 = 0.f, ps1 = 0.f;
        #pragma unroll
        for (int nj = 0; nj < 4; nj++) {
            int j0 = wx*32 + nj*8 + 2*t4;
            float p00 = __expf(sf[nj][0] - mn0);
            float p01 = __expf(sf[nj][1] - mn0);
            float p10 = __expf(sf[nj][2] - mn1);
            float p11 = __expf(sf[nj][3] - mn1);
            ps0 += p00 + p01;
            ps1 += p10 + p11;
            PT[j0*FPAD + mr]       = f2tf32(p00);
            PT[(j0+1)*FPAD + mr]   = f2tf32(p01);
            PT[j0*FPAD + mr+8]     = f2tf32(p10);
            PT[(j0+1)*FPAD + mr+8] = f2tf32(p11);
        }
        ps0 += __shfl_xor_sync(0xffffffffu, ps0, 1);
        ps0 += __shfl_xor_sync(0xffffffffu, ps0, 2);
        ps1 += __shfl_xor_sync(0xffffffffu, ps1, 1);
        ps1 += __shfl_xor_sync(0xffffffffu, ps1, 2);
        if (t4 == 0) {
            SSUM[mr*2 + wx] = ps0;
            SSUM[(mr+8)*2 + wx] = ps1;
        }

        #pragma unroll
        for (int nj = 0; nj < 4; nj++) {
            acc[nj][0] *= corr0; acc[nj][1] *= corr0;
            acc[nj][2] *= corr1; acc[nj][3] *= corr1;
        }
        __syncthreads();

        l0 = l0*corr0 + SSUM[mr*2] + SSUM[mr*2+1];
        l1 = l1*corr1 + SSUM[(mr+8)*2] + SSUM[(mr+8)*2+1];

        #pragma unroll
        for (int kk = 0; kk < 64; kk += 8) {
            unsigned ap[4];
            ap[0] = PT[(kk+t4)*FPAD + mr];
            ap[1] = PT[(kk+t4)*FPAD + mr + 8];
            ap[2] = PT[(kk+t4+4)*FPAD + mr];
            ap[3] = PT[(kk+t4+4)*FPAD + mr + 8];
            #pragma unroll
            for (int nj = 0; nj < 4; nj++) {
                int nc = wx*32 + nj*8 + g;
                unsigned bv[2] = { f2tf32(VB[(kk+t4)*FPAD + nc]),
                                   f2tf32(VB[(kk+t4+4)*FPAD + nc]) };
                mma_tf32(acc[nj], ap, bv);
            }
        }
        __syncthreads();
    }

    float inv0 = 1.f / l0, inv1 = 1.f / l1;
    #pragma unroll
    for (int nj = 0; nj < 4; nj++) {
        int col = h*oColMul + oColAdd + wx*32 + nj*8 + 2*t4;
        long r0 = (long)(qrow0 + mr)*ostride + col;
        long r1 = (long)(qrow0 + mr + 8)*ostride + col;
        *(float2*)&Out[r0] = make_float2(acc[nj][0]*inv0, acc[nj][1]*inv0);
        *(float2*)&Out[r1] = make_float2(acc[nj][2]*inv1, acc[nj][3]*inv1);
    }
}

// ---------------- memories copy ----------------
__global__ void memories_kernel(const float* __restrict__ qkv, float* __restrict__ out)
{
    int idx = blockIdx.x*256 + threadIdx.x;
    if (idx >= 2*HEADS*WIDTH*HD) return;
    int d = idx & 63;
    int i = (idx >> 6) & 511;
    int h = (idx >> 15) & 15;
    int s = idx >> 19;
    out[idx] = qkv[(long)(3584+i)*3072 + (s ? 2048 : 1024) + h*HD + d];
}

// ---------------- new_states ----------------
__global__ void newstates_kernel(const float* __restrict__ gz, const float* __restrict__ bg,
        const float* __restrict__ beta, const float* __restrict__ init_state,
        float* __restrict__ out)
{
    int idx = blockIdx.x*256 + threadIdx.x;
    if (idx >= NST*DIMM) return;
    int c = idx & (DIMM-1);
    float sig = 1.f/(1.f+expf(-beta[c]));
    float z = gz[idx] + bg[c];
    out[idx] = sig*z + (1.f-sig)*init_state[idx];
}

// ---------------- host launch ----------------
static float* symaddr(const void* s)
{
    void* p = nullptr;
    cudaGetSymbolAddress(&p, s);
    return (float*)p;
}

extern "C" void kernel_launch(void* const* d_in, const int* in_sizes, int n_in,
                              void* d_out, int out_size)
{
    const float* x       = (const float*)d_in[0];
    const float* bias    = (const float*)d_in[1];
    const float* gamma   = (const float*)d_in[2];
    const float* w_qkv   = (const float*)d_in[3];
    const float* q_scale = (const float*)d_in[4];
    const float* k_scale = (const float*)d_in[5];
    const float* w_out   = (const float*)d_in[6];
    const float* s_gamma = (const float*)d_in[7];
    const float* w_q2s   = (const float*)d_in[8];
    const float* w_qfs   = (const float*)d_in[9];
    const float* w_sqkv  = (const float*)d_in[10];
    const float* init_st = (const float*)d_in[11];
    const float* pos_ids = (const float*)d_in[12];
    const float* w_sout  = (const float*)d_in[13];
    const float* ts_q    = (const float*)d_in[14];
    const float* ts_k    = (const float*)d_in[15];
    const float* ss_q    = (const float*)d_in[16];
    const float* ss_k    = (const float*)d_in[17];
    const float* fs_q    = (const float*)d_in[18];
    const float* fs_k    = (const float*)d_in[19];
    const float* w_gate  = (const float*)d_in[20];
    const float* b_gate  = (const float*)d_in[21];
    const float* beta    = (const float*)d_in[22];
    float* out = (float*)d_out;

    float* xn   = symaddr(g_xn);
    float* qkv  = symaddr(g_qkv);
    float* q2s  = symaddr(g_q2s);
    float* sqkv = symaddr(g_state_qkv);
    float* st   = symaddr(g_st);
    float* qfsr = symaddr(g_qfs_raw);
    float* qnm  = symaddr(g_qn_main);
    float* knm  = symaddr(g_kn_main);
    float* qnts = symaddr(g_qn_ts);
    float* knts = symaddr(g_kn_ts);
    float* qnss = symaddr(g_qn_ss);
    float* knss = symaddr(g_kn_ss);
    float* qnfs = symaddr(g_qn_fs);
    float* knfs = symaddr(g_kn_fs);
    float* cat  = symaddr(g_cat);
    float* scat = symaddr(g_state_cat);
    float* so   = symaddr(g_so);
    float* zb   = symaddr(g_z);

    // one-time stream/event setup (host objects only; reused across calls)
    static cudaStream_t s1 = nullptr;
    static cudaEvent_t evXn, evQn, evTs, evS1;
    if (!s1) {
        cudaStreamCreateWithFlags(&s1, cudaStreamNonBlocking);
        cudaEventCreateWithFlags(&evXn, cudaEventDisableTiming);
        cudaEventCreateWithFlags(&evQn, cudaEventDisableTiming);
        cudaEventCreateWithFlags(&evTs, cudaEventDisableTiming);
        cudaEventCreateWithFlags(&evS1, cudaEventDisableTiming);
        cudaFuncSetAttribute(flashmma, cudaFuncAttributeMaxDynamicSharedMemorySize, FLASH_SMEM);
        cudaFuncSetAttribute(tgemm, cudaFuncAttributeMaxDynamicSharedMemorySize, TGEMM_SMEM);
    }

    cudaStream_t s0 = 0;   // legacy default (capture origin)

    // ===== stream0: main path =====
    ln_kernel<<<NSEQ, 256, 0, s0>>>(x, gamma, nullptr, xn);
    cudaEventRecord(evXn, s0);

    tgemm<<<dim3(3072/128, NSEQ/128), 256, TGEMM_SMEM, s0>>>(xn, w_qkv, qkv, NSEQ, 3072, DIMM, 0);
    norm_heads<<<dim3(NSEQ, HEADS), 64, 0, s0>>>(qkv, 3072, 0,    0,    q_scale, qnm,  NSEQ);
    norm_heads<<<dim3(NSEQ, HEADS), 64, 0, s0>>>(qkv, 3072, 1024, 0,    k_scale, knm,  NSEQ);
    norm_heads<<<dim3(NST,  HEADS), 64, 0, s0>>>(qkv, 3072, 1024, 3584, fs_k,    knfs, NST);
    cudaEventRecord(evQn, s0);

    flashmma<<<dim3(WIDTH/64, HEADS*NW), 256, FLASH_SMEM, s0>>>(
        qnm, NSEQ, knm, NSEQ, qkv, 3072, HD, 2048, 0, bias,
        cat, 2*DIMM, HD, 0, KEYW, NW);

    // ===== stream1: state branch (forked on evXn) =====
    cudaStreamWaitEvent(s1, evXn, 0);
    ln_kernel<<<NST, 256, 0, s1>>>(init_st, s_gamma, pos_ids, st);
    tgemm<<<dim3(3072/128, NST/128), 256, TGEMM_SMEM, s1>>>(init_st, w_sqkv, sqkv, NST, 3072, DIMM, 0);
    tgemm<<<dim3(DIMM/128, NST/128), 256, TGEMM_SMEM, s1>>>(st, w_qfs, qfsr, NST, DIMM, DIMM, 0);
    tgemm<<<dim3(DIMM/128, NSEQ/128), 256, TGEMM_SMEM, s1>>>(xn, w_q2s, q2s, NSEQ, DIMM, DIMM, 0);

    norm_heads<<<dim3(NSEQ, HEADS), 64, 0, s1>>>(q2s, 1024, 0,    0, ts_q, qnts, NSEQ);
    norm_heads<<<dim3(NST,  HEADS), 64, 0, s1>>>(sqkv, 3072, 1024, 0, ts_k, knts, NST);
    norm_heads<<<dim3(NST,  HEADS), 64, 0, s1>>>(sqkv, 3072, 0,    0, ss_q, qnss, NST);
    norm_heads<<<dim3(NST,  HEADS), 64, 0, s1>>>(sqkv, 3072, 1024, 0, ss_k, knss, NST);
    norm_heads<<<dim3(NST,  HEADS), 64, 0, s1>>>(qfsr, 1024, 0,    0, fs_q, qnfs, NST);

    flashmma<<<dim3(NSEQ/64, HEADS), 256, FLASH_SMEM, s1>>>(
        qnts, NSEQ, knts, NST, sqkv, 3072, HD, 2048, 0, nullptr,
        cat, 2*DIMM, HD, DIMM, NST, 1);
    cudaEventRecord(evTs, s1);

    flashmma<<<dim3(NST/64, HEADS), 256, FLASH_SMEM, s1>>>(
        qnss, NST, knss, NST, sqkv, 3072, HD, 2048, 0, nullptr,
        scat, 2*DIMM, 2*HD, 0, NST, 1);

    cudaStreamWaitEvent(s1, evQn, 0);
    flashmma<<<dim3(NST/64, HEADS), 256, FLASH_SMEM, s1>>>(
        qnfs, NST, knfs, NST, qkv, 3072, HD, 2048, 3584, nullptr,
        scat, 2*DIMM, 2*HD, HD, NST, 1);
    memories_kernel<<<(2*HEADS*WIDTH*HD)/256, 256, 0, s1>>>(qkv, out + (long)NSEQ*DIMM);

    tgemm<<<dim3(DIMM/128, NST/128), 256, TGEMM_SMEM, s1>>>(scat, w_sout, so, NST, DIMM, 2*DIMM, 0);
    tgemm<<<dim3(DIMM/128, NST/128), 256, TGEMM_SMEM, s1>>>(so, w_gate, zb, NST, DIMM, DIMM, 0);
    newstates_kernel<<<(NST*DIMM)/256, 256, 0, s1>>>(zb, b_gate, beta, init_st,
            out + (long)NSEQ*DIMM + 2*HEADS*WIDTH*HD);
    cudaEventRecord(evS1, s1);

    // ===== stream0: output projection (needs flash_main + flash_ts) =====
    cudaStreamWaitEvent(s0, evTs, 0);
    tgemm<<<dim3(DIMM/128, NSEQ/128), 256, TGEMM_SMEM, s0>>>(cat, w_out, out, NSEQ, DIMM, 2*DIMM, 0);

    // join state branch back into the origin stream
    cudaStreamWaitEvent(s0, evS1, 0);
}

// round 14
// speedup vs baseline: 1.2601x; 1.0757x over previous
#include <cuda_runtime.h>
#include <math.h>

#define NSEQ  4096
#define DIMM  1024
#define HEADS 16
#define HD    64
#define WIDTH 512
#define NW    8
#define NST   512
#define KEYW  1024

// ---------------- scratch ----------------
__device__ float g_xn[NSEQ*DIMM];
__device__ float g_qkv[NSEQ*3*DIMM];
__device__ float g_q2s[NSEQ*DIMM];
__device__ float g_state_qkv[NST*3*DIMM];
__device__ float g_st[NST*DIMM];
__device__ float g_qfs_raw[NST*DIMM];

__device__ float g_qn_main[HEADS*NSEQ*HD];
__device__ float g_kn_main[HEADS*NSEQ*HD];
__device__ float g_qn_ts[HEADS*NSEQ*HD];
__device__ float g_kn_ts[HEADS*NST*HD];
__device__ float g_qn_ss[HEADS*NST*HD];
__device__ float g_kn_ss[HEADS*NST*HD];
__device__ float g_qn_fs[HEADS*NST*HD];
__device__ float g_kn_fs[HEADS*NST*HD];

__device__ float g_cat[NSEQ*2*DIMM];
__device__ float g_state_cat[NST*2*DIMM];
__device__ float g_so[NST*DIMM];
__device__ float g_z[NST*DIMM];

// ---------------- layernorm ----------------
__global__ void __launch_bounds__(256) ln_kernel(const float* __restrict__ x,
        const float* __restrict__ gamma, const float* __restrict__ pos,
        float* __restrict__ out)
{
    int row = blockIdx.x;
    const float* xr = x + (long)row*DIMM;
    float* orow = out + (long)row*DIMM;
    __shared__ float red[256];
    float s = 0.f, s2 = 0.f;
    for (int i = threadIdx.x; i < DIMM; i += 256) { float v = xr[i]; s += v; s2 += v*v; }
    red[threadIdx.x] = s; __syncthreads();
    for (int o = 128; o; o >>= 1) { if (threadIdx.x < o) red[threadIdx.x] += red[threadIdx.x+o]; __syncthreads(); }
    float mu = red[0] * (1.f/DIMM);
    __syncthreads();
    red[threadIdx.x] = s2; __syncthreads();
    for (int o = 128; o; o >>= 1) { if (threadIdx.x < o) red[threadIdx.x] += red[threadIdx.x+o]; __syncthreads(); }
    float var = red[0] * (1.f/DIMM) - mu*mu;
    float inv = rsqrtf(var + 1e-5f);
    for (int i = threadIdx.x; i < DIMM; i += 256) {
        float v = (xr[i]-mu)*inv*gamma[i];
        if (pos) v += pos[(long)row*DIMM + i];
        orow[i] = v;
    }
}

// ---------------- TF32 helpers ----------------
__device__ __forceinline__ unsigned f2tf32(float f)
{
    unsigned r;
    asm("cvt.rna.tf32.f32 %0, %1;" : "=r"(r) : "f"(f));
    return r;
}

__device__ __forceinline__ void mma_tf32(float c[4], const unsigned a[4], const unsigned b[2])
{
    asm volatile(
        "mma.sync.aligned.m16n8k8.row.col.f32.tf32.tf32.f32 "
        "{%0,%1,%2,%3}, {%4,%5,%6,%7}, {%8,%9}, {%0,%1,%2,%3};"
        : "+f"(c[0]), "+f"(c[1]), "+f"(c[2]), "+f"(c[3])
        : "r"(a[0]), "r"(a[1]), "r"(a[2]), "r"(a[3]), "r"(b[0]), "r"(b[1]));
}

__device__ __forceinline__ void cp16(float* dst, const float* src)
{
    unsigned d = (unsigned)__cvta_generic_to_shared(dst);
    asm volatile("cp.async.cg.shared.global [%0], [%1], 16;" :: "r"(d), "l"(src));
}

__device__ __forceinline__ void cp16p(float* dst, const float* src, int sz)
{
    unsigned d = (unsigned)__cvta_generic_to_shared(dst);
    asm volatile("cp.async.cg.shared.global [%0], [%1], 16, %2;" :: "r"(d), "l"(src), "r"(sz));
}

// ---------------- TF32 GEMM: cp.async 4-stage pipeline ----------------
#define TG_STAGES 4
#define TG_ASTRIDE 20
#define TG_ATILE (128*TG_ASTRIDE)
#define TG_BTILE (16*132)
#define TGEMM_SMEM (TG_STAGES*(TG_ATILE + TG_BTILE)*4)

__global__ void __launch_bounds__(256) tgemm(const float* __restrict__ A,
        const float* __restrict__ B, float* __restrict__ C,
        int M, int N, int K, int accum)
{
    extern __shared__ float tsm[];
    float* Asm = tsm;
    float* Bsm = tsm + TG_STAGES*TG_ATILE;

    int tid = threadIdx.x;
    int warp = tid >> 5, lane = tid & 31;
    int wy = warp >> 1, wx = warp & 1;
    int g = lane >> 2, t4 = lane & 3;
    int m0 = blockIdx.y*128, n0 = blockIdx.x*128;

    int nkt = K >> 4;

    auto issue = [&](int kt) {
        int buf = kt & (TG_STAGES-1);
        float* as = Asm + buf*TG_ATILE;
        float* bs = Bsm + buf*TG_BTILE;
        int row = tid >> 2, seg = (tid & 3)*4;
        const float* a0 = A + (long)(m0 + row)*K + kt*16 + seg;
        cp16(as + row*TG_ASTRIDE + seg, a0);
        cp16(as + (row+64)*TG_ASTRIDE + seg, a0 + (long)64*K);
        int krow = tid >> 5, col = (tid & 31)*4;
        const float* b0 = B + (long)(kt*16 + krow)*N + n0 + col;
        cp16(bs + krow*132 + col, b0);
        cp16(bs + (krow+8)*132 + col, b0 + (long)8*N);
        asm volatile("cp.async.commit_group;");
    };

    float acc[2][8][4];
    #pragma unroll
    for (int mi = 0; mi < 2; mi++)
        #pragma unroll
        for (int nj = 0; nj < 8; nj++)
            #pragma unroll
            for (int c = 0; c < 4; c++) acc[mi][nj][c] = 0.f;

    #pragma unroll
    for (int s = 0; s < TG_STAGES-1; s++)
        if (s < nkt) issue(s);

    for (int kt = 0; kt < nkt; kt++) {
        asm volatile("cp.async.wait_group %0;" :: "n"(TG_STAGES-2));
        __syncthreads();

        if (kt + TG_STAGES-1 < nkt) issue(kt + TG_STAGES-1);

        int buf = kt & (TG_STAGES-1);
        const float* as = Asm + buf*TG_ATILE;
        const float* bs = Bsm + buf*TG_BTILE;

        #pragma unroll
        for (int ks = 0; ks < 2; ks++) {
            int kk = ks*8;
            unsigned af[2][4], bf[8][2];
            #pragma unroll
            for (int mi = 0; mi < 2; mi++) {
                int mr = wy*32 + mi*16 + g;
                af[mi][0] = f2tf32(as[mr*TG_ASTRIDE + kk + t4]);
                af[mi][1] = f2tf32(as[(mr+8)*TG_ASTRIDE + kk + t4]);
                af[mi][2] = f2tf32(as[mr*TG_ASTRIDE + kk + t4 + 4]);
                af[mi][3] = f2tf32(as[(mr+8)*TG_ASTRIDE + kk + t4 + 4]);
            }
            #pragma unroll
            for (int nj = 0; nj < 8; nj++) {
                int nc = wx*64 + nj*8 + g;
                bf[nj][0] = f2tf32(bs[(kk + t4)*132 + nc]);
                bf[nj][1] = f2tf32(bs[(kk + t4 + 4)*132 + nc]);
            }
            #pragma unroll
            for (int mi = 0; mi < 2; mi++)
                #pragma unroll
                for (int nj = 0; nj < 8; nj++)
                    mma_tf32(acc[mi][nj], af[mi], bf[nj]);
        }
    }

    #pragma unroll
    for (int mi = 0; mi < 2; mi++) {
        #pragma unroll
        for (int nj = 0; nj < 8; nj++) {
            int row = m0 + wy*32 + mi*16 + g;
            int col = n0 + wx*64 + nj*8 + t4*2;
            float* p0 = &C[(long)row*N + col];
            float* p1 = &C[(long)(row+8)*N + col];
            float2 v0 = make_float2(acc[mi][nj][0], acc[mi][nj][1]);
            float2 v1 = make_float2(acc[mi][nj][2], acc[mi][nj][3]);
            if (accum) {
                float2 o0 = *(float2*)p0, o1 = *(float2*)p1;
                v0.x += o0.x; v0.y += o0.y; v1.x += o1.x; v1.y += o1.y;
            }
            *(float2*)p0 = v0;
            *(float2*)p1 = v1;
        }
    }
}

// ---------------- l2norm + scale: warp per (row,head), float2 per lane ----------------
__global__ void __launch_bounds__(256) norm_heads(const float* __restrict__ src,
        int srcStride, int colOff, int rowOff,
        const float* __restrict__ scale, float* __restrict__ dst, int nrows)
{
    int w = threadIdx.x >> 5, lane = threadIdx.x & 31;
    int pair = blockIdx.x*8 + w;              // pair = h*nrows + row (dst-major order)
    int h = pair / nrows;
    int row = pair - h*nrows;
    int d0 = lane*2;

    const float* sp = src + (long)(rowOff+row)*srcStride + colOff + h*HD + d0;
    float2 v = *(const float2*)sp;
    float s = v.x*v.x + v.y*v.y;
    #pragma unroll
    for (int o = 16; o; o >>= 1) s += __shfl_xor_sync(0xffffffffu, s, o);
    float inv = 1.f / fmaxf(sqrtf(s), 1e-12f);
    float2 sc = *(const float2*)(scale + d0);
    float2 r = make_float2(v.x*inv*sc.x, v.y*inv*sc.y);
    *(float2*)(dst + (long)pair*HD + d0) = r;
}

// ---------------- flash attention: cp.async K/V raw, split at fragment load ----------------
#define FPAD 68
#define TILEU (64*FPAD)
#define FLASH_SMEM (6*TILEU*4 + 256*4)

__global__ void __launch_bounds__(256, 2) flashmma(
        const float* __restrict__ Q, int qHeadRows,
        const float* __restrict__ Kh, int kHeadRows,
        const float* __restrict__ Vall, long vstride, int vColHeadMul, int vColAdd,
        int vRowExtra,
        const float* __restrict__ bias,
        float* __restrict__ Out, long ostride, int oColMul, int oColAdd,
        int L, int nwin)
{
    extern __shared__ unsigned usm[];
    unsigned* QHI = usm;
    unsigned* QLO = usm + TILEU;
    float* KR  = (float*)(usm + 2*TILEU);
    float* VR0 = (float*)(usm + 3*TILEU);
    float* VR1 = (float*)(usm + 4*TILEU);
    unsigned* PT = usm + 5*TILEU;
    float* SMAX = (float*)(usm + 6*TILEU);
    float* SSUM = SMAX + 128;

    int tid = threadIdx.x;
    int warp = tid >> 5, lane = tid & 31;
    int wy = warp >> 1, wx = warp & 1;
    int g = lane >> 2, t4 = lane & 3;

    int z = blockIdx.y;
    int h = z / nwin, w = z - h*nwin;
    int winw = qHeadRows / nwin;
    int i0 = blockIdx.x*64;
    int qrow0 = w*winw + i0;
    int kOff = (nwin > 1) ? (w-1)*winw : 0;

    const float* Qblk = Q + ((long)h*qHeadRows + qrow0)*64;
    const float* Kbase = Kh + (long)h*kHeadRows*64;
    const float* Vbase = Vall + vColHeadMul*h + vColAdd;
    const float* biasH = bias ? bias + (long)h*WIDTH*KEYW : nullptr;

    auto issueK = [&](int c0) {
        #pragma unroll
        for (int t = 0; t < 4; t++) {
            int c4 = tid + t*256;
            int key = c4 >> 4, seg = (c4 & 15)*4;
            int kr = kOff + c0 + key;
            cp16p(KR + key*FPAD + seg, Kbase + (long)kr*64 + seg, (kr >= 0) ? 16 : 0);
        }
        asm volatile("cp.async.commit_group;");
    };
    auto issueV = [&](int c0, float* VB) {
        #pragma unroll
        for (int t = 0; t < 4; t++) {
            int c4 = tid + t*256;
            int key = c4 >> 4, seg = (c4 & 15)*4;
            int kr = kOff + c0 + key;
            cp16p(VB + key*FPAD + seg, Vbase + (long)(kr + vRowExtra)*vstride + seg,
                  (kr >= 0) ? 16 : 0);
        }
        asm volatile("cp.async.commit_group;");
    };

    #pragma unroll
    for (int t = 0; t < 16; t++) {
        int e = tid + t*256;
        int r = e >> 6, c = e & 63;
        float v = Qblk[(long)r*64 + c];
        unsigned hi = f2tf32(v);
        QHI[c*FPAD + r] = hi;
        QLO[c*FPAD + r] = f2tf32(v - __uint_as_float(hi));
    }

    int mr = wy*16 + g;
    float m0r = -3.402823466e38f, m1r = -3.402823466e38f;
    float l0 = 0.f, l1 = 0.f;
    float acc[4][4];
    #pragma unroll
    for (int nj = 0; nj < 4; nj++)
        #pragma unroll
        for (int c = 0; c < 4; c++) acc[nj][c] = 0.f;

    int Lq = biasH ? (i0 + 576) : L;
    if (Lq > L) Lq = L;
    int nch = (Lq + 63) >> 6;

    issueV(0, VR0);
    issueK(0);

    for (int ci = 0; ci < nch; ci++) {
        int c0 = ci << 6;
        float* VB = (ci & 1) ? VR1 : VR0;
        bool more = (ci + 1 < nch);

        if (more) {
            issueV(c0 + 64, (ci & 1) ? VR0 : VR1);
            asm volatile("cp.async.wait_group 1;");
        } else {
            asm volatile("cp.async.wait_group 0;");
        }
        __syncthreads();

        float sf[4][4];
        #pragma unroll
        for (int nj = 0; nj < 4; nj++)
            #pragma unroll
            for (int c = 0; c < 4; c++) sf[nj][c] = 0.f;

        #pragma unroll
        for (int kk = 0; kk < 64; kk += 8) {
            unsigned ahi[4], alo[4];
            ahi[0] = QHI[(kk+t4)*FPAD + mr];
            ahi[1] = QHI[(kk+t4)*FPAD + mr + 8];
            ahi[2] = QHI[(kk+t4+4)*FPAD + mr];
            ahi[3] = QHI[(kk+t4+4)*FPAD + mr + 8];
            alo[0] = QLO[(kk+t4)*FPAD + mr];
            alo[1] = QLO[(kk+t4)*FPAD + mr + 8];
            alo[2] = QLO[(kk+t4+4)*FPAD + mr];
            alo[3] = QLO[(kk+t4+4)*FPAD + mr + 8];
            #pragma unroll
            for (int nj = 0; nj < 4; nj++) {
                int nc = wx*32 + nj*8 + g;
                float k0 = KR[nc*FPAD + kk + t4];
                float k1 = KR[nc*FPAD + kk + t4 + 4];
                unsigned bhi[2] = { f2tf32(k0), f2tf32(k1) };
                unsigned blo[2] = { f2tf32(k0 - __uint_as_float(bhi[0])),
                                    f2tf32(k1 - __uint_as_float(bhi[1])) };
                mma_tf32(sf[nj], ahi, bhi);
                mma_tf32(sf[nj], alo, bhi);
                mma_tf32(sf[nj], ahi, blo);
            }
        }

        int ir0 = i0 + mr, ir1 = ir0 + 8;
        #pragma unroll
        for (int nj = 0; nj < 4; nj++) {
            int j0 = c0 + wx*32 + nj*8 + 2*t4;
            #pragma unroll
            for (int c = 0; c < 4; c++) sf[nj][c] *= 8.f;
            if (biasH) {
                float2 b0 = *(const float2*)&biasH[(long)ir0*KEYW + j0];
                float2 b1 = *(const float2*)&biasH[(long)ir1*KEYW + j0];
                sf[nj][0] += b0.x; sf[nj][1] += b0.y;
                sf[nj][2] += b1.x; sf[nj][3] += b1.y;
                if (j0     > ir0 + 512) sf[nj][0] = -3.402823466e38f;
                if (j0 + 1 > ir0 + 512) sf[nj][1] = -3.402823466e38f;
                if (j0     > ir1 + 512) sf[nj][2] = -3.402823466e38f;
                if (j0 + 1 > ir1 + 512) sf[nj][3] = -3.402823466e38f;
            }
        }

        float pm0 = -3.402823466e38f, pm1 = -3.402823466e38f;
        #pragma unroll
        for (int nj = 0; nj < 4; nj++) {
            pm0 = fmaxf(pm0, fmaxf(sf[nj][0], sf[nj][1]));
            pm1 = fmaxf(pm1, fmaxf(sf[nj][2], sf[nj][3]));
        }
        pm0 = fmaxf(pm0, __shfl_xor_sync(0xffffffffu, pm0, 1));
        pm0 = fmaxf(pm0, __shfl_xor_sync(0xffffffffu, pm0, 2));
        pm1 = fmaxf(pm1, __shfl_xor_sync(0xffffffffu, pm1, 1));
        pm1 = fmaxf(pm1, __shfl_xor_sync(0xffffffffu, pm1, 2));
        if (t4 == 0) {
            SMAX[mr*2 + wx] = pm0;
            SMAX[(mr+8)*2 + wx] = pm1;
        }
        __syncthreads();

        if (more) issueK(c0 + 64);

        float cmax0 = fmaxf(SMAX[mr*2], SMAX[mr*2+1]);
        float cmax1 = fmaxf(SMAX[(mr+8)*2], SMAX[(mr+8)*2+1]);

        float mn0 = fmaxf(m0r, cmax0);
        float mn1 = fmaxf(m1r, cmax1);
        float corr0 = __expf(m0r - mn0);
        float corr1 = __expf(m1r - mn1);
        m0r = mn0; m1r = mn1;

        float ps0 = 0.f, ps1 = 0.f;
        #pragma unroll
        for (int nj = 0; nj < 4; nj++) {
            int j0 = wx*32 + nj*8 + 2*t4;
            float p00 = __expf(sf[nj][0] - mn0);
            float p01 = __expf(sf[nj][1] - mn0);
            float p10 = __expf(sf[nj][2] - mn1);
            float p11 = __expf(sf[nj][3] - mn1);
            ps0 += p00 + p01;
            ps1 += p10 + p11;
            PT[j0*FPAD + mr]       = f2tf32(p00);
            PT[(j0+1)*FPAD + mr]   = f2tf32(p01);
            PT[j0*FPAD + mr+8]     = f2tf32(p10);
            PT[(j0+1)*FPAD + mr+8] = f2tf32(p11);
        }
        ps0 += __shfl_xor_sync(0xffffffffu, ps0, 1);
        ps0 += __shfl_xor_sync(0xffffffffu, ps0, 2);
        ps1 += __shfl_xor_sync(0xffffffffu, ps1, 1);
        ps1 += __shfl_xor_sync(0xffffffffu, ps1, 2);
        if (t4 == 0) {
            SSUM[mr*2 + wx] = ps0;
            SSUM[(mr+8)*2 + wx] = ps1;
        }

        #pragma unroll
        for (int nj = 0; nj < 4; nj++) {
            acc[nj][0] *= corr0; acc[nj][1] *= corr0;
            acc[nj][2] *= corr1; acc[nj][3] *= corr1;
        }
        __syncthreads();

        l0 = l0*corr0 + SSUM[mr*2] + SSUM[mr*2+1];
        l1 = l1*corr1 + SSUM[(mr+8)*2] + SSUM[(mr+8)*2+1];

        #pragma unroll
        for (int kk = 0; kk < 64; kk += 8) {
            unsigned ap[4];
            ap[0] = PT[(kk+t4)*FPAD + mr];
            ap[1] = PT[(kk+t4)*FPAD + mr + 8];
            ap[2] = PT[(kk+t4+4)*FPAD + mr];
            ap[3] = PT[(kk+t4+4)*FPAD + mr + 8];
            #pragma unroll
            for (int nj = 0; nj < 4; nj++) {
                int nc = wx*32 + nj*8 + g;
                unsigned bv[2] = { f2tf32(VB[(kk+t4)*FPAD + nc]),
                                   f2tf32(VB[(kk+t4+4)*FPAD + nc]) };
                mma_tf32(acc[nj], ap, bv);
            }
        }
        __syncthreads();
    }

    float inv0 = 1.f / l0, inv1 = 1.f / l1;
    #pragma unroll
    for (int nj = 0; nj < 4; nj++) {
        int col = h*oColMul + oColAdd + wx*32 + nj*8 + 2*t4;
        long r0 = (long)(qrow0 + mr)*ostride + col;
        long r1 = (long)(qrow0 + mr + 8)*ostride + col;
        *(float2*)&Out[r0] = make_float2(acc[nj][0]*inv0, acc[nj][1]*inv0);
        *(float2*)&Out[r1] = make_float2(acc[nj][2]*inv1, acc[nj][3]*inv1);
    }
}

// ---------------- memories copy ----------------
__global__ void memories_kernel(const float* __restrict__ qkv, float* __restrict__ out)
{
    int idx = blockIdx.x*256 + threadIdx.x;
    if (idx >= 2*HEADS*WIDTH*HD) return;
    int d = idx & 63;
    int i = (idx >> 6) & 511;
    int h = (idx >> 15) & 15;
    int s = idx >> 19;
    out[idx] = qkv[(long)(3584+i)*3072 + (s ? 2048 : 1024) + h*HD + d];
}

// ---------------- new_states ----------------
__global__ void newstates_kernel(const float* __restrict__ gz, const float* __restrict__ bg,
        const float* __restrict__ beta, const float* __restrict__ init_state,
        float* __restrict__ out)
{
    int idx = blockIdx.x*256 + threadIdx.x;
    if (idx >= NST*DIMM) return;
    int c = idx & (DIMM-1);
    float sig = 1.f/(1.f+expf(-beta[c]));
    float z = gz[idx] + bg[c];
    out[idx] = sig*z + (1.f-sig)*init_state[idx];
}

// ---------------- host launch ----------------
static float* symaddr(const void* s)
{
    void* p = nullptr;
    cudaGetSymbolAddress(&p, s);
    return (float*)p;
}

extern "C" void kernel_launch(void* const* d_in, const int* in_sizes, int n_in,
                              void* d_out, int out_size)
{
    const float* x       = (const float*)d_in[0];
    const float* bias    = (const float*)d_in[1];
    const float* gamma   = (const float*)d_in[2];
    const float* w_qkv   = (const float*)d_in[3];
    const float* q_scale = (const float*)d_in[4];
    const float* k_scale = (const float*)d_in[5];
    const float* w_out   = (const float*)d_in[6];
    const float* s_gamma = (const float*)d_in[7];
    const float* w_q2s   = (const float*)d_in[8];
    const float* w_qfs   = (const float*)d_in[9];
    const float* w_sqkv  = (const float*)d_in[10];
    const float* init_st = (const float*)d_in[11];
    const float* pos_ids = (const float*)d_in[12];
    const float* w_sout  = (const float*)d_in[13];
    const float* ts_q    = (const float*)d_in[14];
    const float* ts_k    = (const float*)d_in[15];
    const float* ss_q    = (const float*)d_in[16];
    const float* ss_k    = (const float*)d_in[17];
    const float* fs_q    = (const float*)d_in[18];
    const float* fs_k    = (const float*)d_in[19];
    const float* w_gate  = (const float*)d_in[20];
    const float* b_gate  = (const float*)d_in[21];
    const float* beta    = (const float*)d_in[22];
    float* out = (float*)d_out;

    float* xn   = symaddr(g_xn);
    float* qkv  = symaddr(g_qkv);
    float* q2s  = symaddr(g_q2s);
    float* sqkv = symaddr(g_state_qkv);
    float* st   = symaddr(g_st);
    float* qfsr = symaddr(g_qfs_raw);
    float* qnm  = symaddr(g_qn_main);
    float* knm  = symaddr(g_kn_main);
    float* qnts = symaddr(g_qn_ts);
    float* knts = symaddr(g_kn_ts);
    float* qnss = symaddr(g_qn_ss);
    float* knss = symaddr(g_kn_ss);
    float* qnfs = symaddr(g_qn_fs);
    float* knfs = symaddr(g_kn_fs);
    float* cat  = symaddr(g_cat);
    float* scat = symaddr(g_state_cat);
    float* so   = symaddr(g_so);
    float* zb   = symaddr(g_z);

    static cudaStream_t s1 = nullptr;
    static cudaEvent_t evXn, evQn, evTs, evS1;
    if (!s1) {
        cudaStreamCreateWithFlags(&s1, cudaStreamNonBlocking);
        cudaEventCreateWithFlags(&evXn, cudaEventDisableTiming);
        cudaEventCreateWithFlags(&evQn, cudaEventDisableTiming);
        cudaEventCreateWithFlags(&evTs, cudaEventDisableTiming);
        cudaEventCreateWithFlags(&evS1, cudaEventDisableTiming);
        cudaFuncSetAttribute(flashmma, cudaFuncAttributeMaxDynamicSharedMemorySize, FLASH_SMEM);
        cudaFuncSetAttribute(tgemm, cudaFuncAttributeMaxDynamicSharedMemorySize, TGEMM_SMEM);
    }

    cudaStream_t s0 = 0;

    // ===== stream0: main path =====
    ln_kernel<<<NSEQ, 256, 0, s0>>>(x, gamma, nullptr, xn);
    cudaEventRecord(evXn, s0);

    tgemm<<<dim3(3072/128, NSEQ/128), 256, TGEMM_SMEM, s0>>>(xn, w_qkv, qkv, NSEQ, 3072, DIMM, 0);
    norm_heads<<<NSEQ*HEADS/8, 256, 0, s0>>>(qkv, 3072, 0,    0,    q_scale, qnm,  NSEQ);
    norm_heads<<<NSEQ*HEADS/8, 256, 0, s0>>>(qkv, 3072, 1024, 0,    k_scale, knm,  NSEQ);
    norm_heads<<<NST*HEADS/8,  256, 0, s0>>>(qkv, 3072, 1024, 3584, fs_k,    knfs, NST);
    cudaEventRecord(evQn, s0);

    flashmma<<<dim3(WIDTH/64, HEADS*NW), 256, FLASH_SMEM, s0>>>(
        qnm, NSEQ, knm, NSEQ, qkv, 3072, HD, 2048, 0, bias,
        cat, 2*DIMM, HD, 0, KEYW, NW);

    // ===== stream1: state branch =====
    cudaStreamWaitEvent(s1, evXn, 0);
    ln_kernel<<<NST, 256, 0, s1>>>(init_st, s_gamma, pos_ids, st);
    tgemm<<<dim3(3072/128, NST/128), 256, TGEMM_SMEM, s1>>>(init_st, w_sqkv, sqkv, NST, 3072, DIMM, 0);
    tgemm<<<dim3(DIMM/128, NST/128), 256, TGEMM_SMEM, s1>>>(st, w_qfs, qfsr, NST, DIMM, DIMM, 0);
    tgemm<<<dim3(DIMM/128, NSEQ/128), 256, TGEMM_SMEM, s1>>>(xn, w_q2s, q2s, NSEQ, DIMM, DIMM, 0);

    norm_heads<<<NSEQ*HEADS/8, 256, 0, s1>>>(q2s, 1024, 0,    0, ts_q, qnts, NSEQ);
    norm_heads<<<NST*HEADS/8,  256, 0, s1>>>(sqkv, 3072, 1024, 0, ts_k, knts, NST);
    norm_heads<<<NST*HEADS/8,  256, 0, s1>>>(sqkv, 3072, 0,    0, ss_q, qnss, NST);
    norm_heads<<<NST*HEADS/8,  256, 0, s1>>>(sqkv, 3072, 1024, 0, ss_k, knss, NST);
    norm_heads<<<NST*HEADS/8,  256, 0, s1>>>(qfsr, 1024, 0,    0, fs_q, qnfs, NST);

    flashmma<<<dim3(NSEQ/64, HEADS), 256, FLASH_SMEM, s1>>>(
        qnts, NSEQ, knts, NST, sqkv, 3072, HD, 2048, 0, nullptr,
        cat, 2*DIMM, HD, DIMM, NST, 1);
    cudaEventRecord(evTs, s1);

    flashmma<<<dim3(NST/64, HEADS), 256, FLASH_SMEM, s1>>>(
        qnss, NST, knss, NST, sqkv, 3072, HD, 2048, 0, nullptr,
        scat, 2*DIMM, 2*HD, 0, NST, 1);

    cudaStreamWaitEvent(s1, evQn, 0);
    flashmma<<<dim3(NST/64, HEADS), 256, FLASH_SMEM, s1>>>(
        qnfs, NST, knfs, NST, qkv, 3072, HD, 2048, 3584, nullptr,
        scat, 2*DIMM, 2*HD, HD, NST, 1);
    memories_kernel<<<(2*HEADS*WIDTH*HD)/256, 256, 0, s1>>>(qkv, out + (long)NSEQ*DIMM);

    tgemm<<<dim3(DIMM/128, NST/128), 256, TGEMM_SMEM, s1>>>(scat, w_sout, so, NST, DIMM, 2*DIMM, 0);
    tgemm<<<dim3(DIMM/128, NST/128), 256, TGEMM_SMEM, s1>>>(so, w_gate, zb, NST, DIMM, DIMM, 0);
    newstates_kernel<<<(NST*DIMM)/256, 256, 0, s1>>>(zb, b_gate, beta, init_st,
            out + (long)NSEQ*DIMM + 2*HEADS*WIDTH*HD);
    cudaEventRecord(evS1, s1);

    // ===== stream0: output projection =====
    cudaStreamWaitEvent(s0, evTs, 0);
    tgemm<<<dim3(DIMM/128, NSEQ/128), 256, TGEMM_SMEM, s0>>>(cat, w_out, out, NSEQ, DIMM, 2*DIMM, 0);

    cudaStreamWaitEvent(s0, evS1, 0);
}